// round 9
// baseline (speedup 1.0000x reference)
#include <cuda_runtime.h>
#include <cstdint>
#include <math.h>

#define BATCH    4
#define SEQLEN   2048
#define DMODEL   1024
#define DSTATE   64
#define DCONV    4
#define HEADDIM  64
#define DINNER   2048
#define NH       32
#define CONVDIM  2176            // DINNER + 2*DSTATE
#define NPROJ    4256            // 2*DINNER + 2*DSTATE + NH
#define MROWS    (BATCH*SEQLEN)  // 8192

// ---------------- scratch (device globals; no allocation allowed) ----------
__device__ float g_zxbcdt[(size_t)MROWS * NPROJ];   // 139.5 MB
__device__ float g_xbc  [(size_t)MROWS * CONVDIM];  // 71.3 MB
__device__ float g_dt   [(size_t)MROWS * NH];
__device__ float g_y    [(size_t)MROWS * DINNER];   // 67 MB

// ================= tf32 mma.sync helpers (base sm_103 target OK) ===========
__device__ __forceinline__ void split_tf32(float v, uint32_t& hi, uint32_t& lo) {
    asm("cvt.rna.tf32.f32 %0, %1;" : "=r"(hi) : "f"(v));
    const float h = __uint_as_float(hi);
    const float l = v - h;
    asm("cvt.rna.tf32.f32 %0, %1;" : "=r"(lo) : "f"(l));
}
__device__ __forceinline__ void mma_tf32(float* c, const uint32_t* a, const uint32_t* b) {
    asm volatile(
        "mma.sync.aligned.m16n8k8.row.col.f32.tf32.tf32.f32 "
        "{%0,%1,%2,%3}, {%4,%5,%6,%7}, {%8,%9}, {%0,%1,%2,%3};\n"
        : "+f"(c[0]), "+f"(c[1]), "+f"(c[2]), "+f"(c[3])
        : "r"(a[0]), "r"(a[1]), "r"(a[2]), "r"(a[3]), "r"(b[0]), "r"(b[1]));
}

// ================= 3xTF32 GEMM: C[M,N] = A[M,K] @ B[K,N] ===================
// BM=BN=128, BK=16, 256 threads (8 warps, 4x2 warp grid, 32x64 per warp).
// fp32 in smem; hi/lo tf32 split in registers; 3 mma passes (AhBh+AhBl+AlBh).
// Requires M%128==0, K%16==0, N%4==0. N edge guarded.
#define GBM 128
#define GBN 128
#define GBK 16
#define GPAD 4
#define GSTRIDE (GBK + GPAD)     // 20 floats: conflict-free fragment loads

__global__ __launch_bounds__(256, 1) void gemm_mma_kernel(
    const float* __restrict__ A, const float* __restrict__ B,
    float* __restrict__ C, int M, int N, int K)
{
    __shared__ __align__(16) float As[GBM][GSTRIDE];
    __shared__ __align__(16) float Bs[GBN][GSTRIDE];   // Bs[n][k]

    const int tid = threadIdx.x;
    const int wid = tid >> 5;
    const int lane = tid & 31;
    const int lr = lane >> 2;     // 0..7
    const int lc = lane & 3;      // 0..3
    const int wM = (wid & 3) * 32;
    const int wN = (wid >> 2) * 64;
    const int rowBase = blockIdx.x * GBM;   // same-y CTAs adjacent in x -> B panel reuse in L2
    const int colBase = blockIdx.y * GBN;
    const int KT = K / GBK;

    // global load maps
    const int aRow = tid >> 1;              // 0..127
    const int aK4  = (tid & 1) * 8;         // 0 or 8
    const float* Aptr = A + (size_t)(rowBase + aRow) * K + aK4;
    const int bK  = tid >> 5;               // 0..7 (and +8 on 2nd fetch)
    const int bN4 = (tid & 31) * 4;
    const bool bOk = (colBase + bN4) < N;
    const float* Bptr = B + colBase + bN4;

    float acc[2][8][4];
    #pragma unroll
    for (int mt = 0; mt < 2; mt++)
        #pragma unroll
        for (int nt = 0; nt < 8; nt++)
            #pragma unroll
            for (int q = 0; q < 4; q++) acc[mt][nt][q] = 0.f;

    float4 aR[2], bR[2];
    // prologue: fetch tile 0
    aR[0] = *(const float4*)(Aptr);
    aR[1] = *(const float4*)(Aptr + 4);
    bR[0] = bOk ? *(const float4*)(Bptr + (size_t)bK * N)       : make_float4(0,0,0,0);
    bR[1] = bOk ? *(const float4*)(Bptr + (size_t)(bK + 8) * N) : make_float4(0,0,0,0);

    for (int kt = 0; kt < KT; kt++) {
        __syncthreads();     // previous tile fully consumed
        // store staged registers to smem
        *(float4*)&As[aRow][aK4]     = aR[0];
        *(float4*)&As[aRow][aK4 + 4] = aR[1];
        #pragma unroll
        for (int j = 0; j < 4; j++) {
            Bs[bN4 + j][bK]     = ((const float*)&bR[0])[j];
            Bs[bN4 + j][bK + 8] = ((const float*)&bR[1])[j];
        }
        __syncthreads();

        // prefetch next tile into registers (hides L2/DRAM behind mma work)
        if (kt + 1 < KT) {
            const float* ap = Aptr + (kt + 1) * GBK;
            aR[0] = *(const float4*)(ap);
            aR[1] = *(const float4*)(ap + 4);
            const size_t kb = (size_t)(kt + 1) * GBK;
            bR[0] = bOk ? *(const float4*)(Bptr + (kb + bK) * N)     : make_float4(0,0,0,0);
            bR[1] = bOk ? *(const float4*)(Bptr + (kb + bK + 8) * N) : make_float4(0,0,0,0);
        }

        // compute: 2 k-steps of 8
        #pragma unroll
        for (int ks = 0; ks < 2; ks++) {
            const int kb = ks * 8;
            uint32_t ahi[2][4], alo[2][4];
            #pragma unroll
            for (int mt = 0; mt < 2; mt++) {
                const int r0 = wM + mt * 16 + lr;
                split_tf32(As[r0    ][kb + lc    ], ahi[mt][0], alo[mt][0]);
                split_tf32(As[r0 + 8][kb + lc    ], ahi[mt][1], alo[mt][1]);
                split_tf32(As[r0    ][kb + lc + 4], ahi[mt][2], alo[mt][2]);
                split_tf32(As[r0 + 8][kb + lc + 4], ahi[mt][3], alo[mt][3]);
            }
            uint32_t bhi[8][2], blo[8][2];
            #pragma unroll
            for (int nt = 0; nt < 8; nt++) {
                const int n0 = wN + nt * 8 + lr;
                split_tf32(Bs[n0][kb + lc    ], bhi[nt][0], blo[nt][0]);
                split_tf32(Bs[n0][kb + lc + 4], bhi[nt][1], blo[nt][1]);
            }
            #pragma unroll
            for (int mt = 0; mt < 2; mt++)
                #pragma unroll
                for (int nt = 0; nt < 8; nt++) {
                    mma_tf32(acc[mt][nt], ahi[mt], bhi[nt]);
                    mma_tf32(acc[mt][nt], ahi[mt], blo[nt]);
                    mma_tf32(acc[mt][nt], alo[mt], bhi[nt]);
                }
        }
    }

    // epilogue
    #pragma unroll
    for (int mt = 0; mt < 2; mt++) {
        const int r = rowBase + wM + mt * 16 + lr;
        #pragma unroll
        for (int nt = 0; nt < 8; nt++) {
            const int cl = colBase + wN + nt * 8 + 2 * lc;
            if (cl < N) {
                *(float2*)(C + (size_t)r * N + cl) =
                    make_float2(acc[mt][nt][0], acc[mt][nt][1]);
                *(float2*)(C + (size_t)(r + 8) * N + cl) =
                    make_float2(acc[mt][nt][2], acc[mt][nt][3]);
            }
        }
    }
}

// ---------------- causal depthwise conv1d (k=4) + bias + SiLU --------------
__global__ __launch_bounds__(256) void conv_kernel(
    const float* __restrict__ conv_w, const float* __restrict__ conv_b)
{
    const int l = blockIdx.x;
    const int b = blockIdx.y;
    const size_t orow = (size_t)(b * SEQLEN + l);

    for (int c = threadIdx.x; c < CONVDIM; c += 256) {
        float s = conv_b[c];
        #pragma unroll
        for (int k = 0; k < DCONV; k++) {
            const int ls = l - (DCONV - 1) + k;
            if (ls >= 0)
                s = fmaf(g_zxbcdt[((size_t)(b * SEQLEN + ls)) * NPROJ + DINNER + c],
                         conv_w[c * DCONV + k], s);
        }
        const float sil = s / (1.f + __expf(-s));
        g_xbc[orow * CONVDIM + c] = sil;
    }
}

// ---------------- dt = softplus(dt_raw + dt_bias) --------------------------
__global__ __launch_bounds__(256) void dt_kernel(const float* __restrict__ dt_bias)
{
    const int i = blockIdx.x * 256 + threadIdx.x;   // over MROWS*NH
    if (i >= MROWS * NH) return;
    const int h = i & (NH - 1);
    const int row = i >> 5;
    const float v = g_zxbcdt[(size_t)row * NPROJ + (DINNER + CONVDIM) + h] + dt_bias[h];
    g_dt[i] = (v > 20.f) ? v : log1pf(expf(v));
}

// ---------------- sequential selective scan (smem-staged chunks) -----------
// Block = one (b, h). 512 threads: p = tid>>3 (0..63), nc = tid&7 (8 states).
// B/C/x/dt staged cooperatively into smem in 16-step chunks (kills the
// 8-64x redundant L1 traffic of per-thread global loads).
#define SCHUNK 16
__global__ __launch_bounds__(512) void scan_kernel(
    const float* __restrict__ A_log, const float* __restrict__ Dv)
{
    __shared__ float sB[SCHUNK][DSTATE];
    __shared__ float sC[SCHUNK][DSTATE];
    __shared__ float sx[SCHUNK][HEADDIM];
    __shared__ float sdt[SCHUNK];

    const int bh = blockIdx.x;
    const int b = bh >> 5, h = bh & (NH - 1);
    const int tid = threadIdx.x;
    const int p  = tid >> 3;
    const int nc = tid & 7;
    const int n0 = nc * 8;

    const float Aneg = -__expf(A_log[h]);
    const float Dh   = Dv[h];

    const float* dptr = g_dt + (size_t)b * SEQLEN * NH + h;
    float*       yptr = g_y  + (size_t)b * SEQLEN * DINNER + h * HEADDIM + p;

    float hs[8];
    #pragma unroll
    for (int i = 0; i < 8; i++) hs[i] = 0.f;

    for (int t0 = 0; t0 < SEQLEN; t0 += SCHUNK) {
        __syncthreads();    // previous chunk fully consumed
        // cooperative stage: 16 steps x 64 floats each of B, C, x
        #pragma unroll
        for (int r = 0; r < 2; r++) {
            const int idx = tid + r * 512;       // 0..1023
            const int t = idx >> 6, j = idx & 63;
            const size_t rb = (size_t)(b * SEQLEN + t0 + t) * CONVDIM;
            sB[t][j] = g_xbc[rb + DINNER + j];
            sC[t][j] = g_xbc[rb + DINNER + DSTATE + j];
            sx[t][j] = g_xbc[rb + h * HEADDIM + j];
        }
        if (tid < SCHUNK) sdt[tid] = dptr[(size_t)(t0 + tid) * NH];
        __syncthreads();

        #pragma unroll 4
        for (int tt = 0; tt < SCHUNK; tt++) {
            const float df = sdt[tt];
            const float xf = sx[tt][p];
            const float dA = __expf(df * Aneg);
            const float coef = df * xf;
            const float4 b0 = *(const float4*)&sB[tt][n0];
            const float4 b1 = *(const float4*)&sB[tt][n0 + 4];
            const float4 c0 = *(const float4*)&sC[tt][n0];
            const float4 c1 = *(const float4*)&sC[tt][n0 + 4];
            float acc = 0.f;
            hs[0] = fmaf(hs[0], dA, coef * b0.x);  acc = fmaf(hs[0], c0.x, acc);
            hs[1] = fmaf(hs[1], dA, coef * b0.y);  acc = fmaf(hs[1], c0.y, acc);
            hs[2] = fmaf(hs[2], dA, coef * b0.z);  acc = fmaf(hs[2], c0.z, acc);
            hs[3] = fmaf(hs[3], dA, coef * b0.w);  acc = fmaf(hs[3], c0.w, acc);
            hs[4] = fmaf(hs[4], dA, coef * b1.x);  acc = fmaf(hs[4], c1.x, acc);
            hs[5] = fmaf(hs[5], dA, coef * b1.y);  acc = fmaf(hs[5], c1.y, acc);
            hs[6] = fmaf(hs[6], dA, coef * b1.z);  acc = fmaf(hs[6], c1.z, acc);
            hs[7] = fmaf(hs[7], dA, coef * b1.w);  acc = fmaf(hs[7], c1.w, acc);
            acc += __shfl_xor_sync(0xffffffffu, acc, 1);
            acc += __shfl_xor_sync(0xffffffffu, acc, 2);
            acc += __shfl_xor_sync(0xffffffffu, acc, 4);
            if (nc == 0) yptr[(size_t)(t0 + tt) * DINNER] = acc + Dh * xf;
        }
    }
}

// ---------------- y = rmsnorm(y * silu(z)) * norm_w (in place) -------------
__global__ __launch_bounds__(256) void gatenorm_kernel(const float* __restrict__ norm_w)
{
    const int row = blockIdx.x;
    const float* zrow = g_zxbcdt + (size_t)row * NPROJ;   // z = first DINNER cols
    float* yrow = g_y + (size_t)row * DINNER;

    float v[8];
    float ss = 0.f;
    #pragma unroll
    for (int j = 0; j < 8; j++) {
        const int i = threadIdx.x + j * 256;
        const float z = zrow[i];
        const float g = yrow[i] * (z / (1.f + __expf(-z)));
        v[j] = g;
        ss = fmaf(g, g, ss);
    }
    #pragma unroll
    for (int o = 16; o; o >>= 1) ss += __shfl_xor_sync(0xffffffffu, ss, o);

    __shared__ float red[8];
    __shared__ float s_rstd;
    if ((threadIdx.x & 31) == 0) red[threadIdx.x >> 5] = ss;
    __syncthreads();
    if (threadIdx.x == 0) {
        float t = 0.f;
        #pragma unroll
        for (int w = 0; w < 8; w++) t += red[w];
        s_rstd = rsqrtf(t / (float)DINNER + 1e-5f);
    }
    __syncthreads();
    const float rstd = s_rstd;

    #pragma unroll
    for (int j = 0; j < 8; j++) {
        const int i = threadIdx.x + j * 256;
        yrow[i] = v[j] * rstd * norm_w[i];
    }
}

// ---------------- launch ----------------------------------------------------
extern "C" void kernel_launch(void* const* d_in, const int* in_sizes, int n_in,
                              void* d_out, int out_size)
{
    const float* x       = (const float*)d_in[0];
    const float* W_in    = (const float*)d_in[1];
    const float* conv_w  = (const float*)d_in[2];
    const float* conv_b  = (const float*)d_in[3];
    const float* dt_bias = (const float*)d_in[4];
    const float* A_log   = (const float*)d_in[5];
    const float* Dvec    = (const float*)d_in[6];
    const float* norm_w  = (const float*)d_in[7];
    const float* W_out   = (const float*)d_in[8];
    float* out = (float*)d_out;

    void *p_zx, *p_y;
    cudaGetSymbolAddress(&p_zx, g_zxbcdt);
    cudaGetSymbolAddress(&p_y,  g_y);
    float* zx = (float*)p_zx;
    float* y  = (float*)p_y;

    // 1) in-projection: zxbcdt = x @ W_in   [8192,1024]@[1024,4256]
    {
        dim3 grid(MROWS / GBM, (NPROJ + GBN - 1) / GBN);
        gemm_mma_kernel<<<grid, 256>>>(x, W_in, zx, MROWS, NPROJ, DMODEL);
    }
    // 2) conv + SiLU
    conv_kernel<<<dim3(SEQLEN, BATCH), 256>>>(conv_w, conv_b);
    // 3) dt softplus
    dt_kernel<<<(MROWS * NH + 255) / 256, 256>>>(dt_bias);
    // 4) selective scan
    scan_kernel<<<BATCH * NH, 512>>>(A_log, Dvec);
    // 5) gate + rmsnorm (in place on g_y)
    gatenorm_kernel<<<MROWS, 256>>>(norm_w);
    // 6) out-projection: out = y @ W_out   [8192,2048]@[2048,1024]
    {
        dim3 grid(MROWS / GBM, DMODEL / GBN);
        gemm_mma_kernel<<<grid, 256>>>(y, W_out, out, MROWS, DMODEL, DINNER);
    }
}